// round 1
// baseline (speedup 1.0000x reference)
#include <cuda_runtime.h>
#include <cuda_bf16.h>
#include <math.h>

// Problem constants
#define BB 128
#define TT 2048
#define FF 80
#define NCLS 10
#define HH 32
#define MROWS (BB*TT)          // 262144
#define EPSBN 1e-5f

// ---------------- scratch (static __device__ arrays; no allocation) -------
__device__ float g_y1[(size_t)MROWS * 256];
__device__ float g_y2[(size_t)MROWS * 128];
__device__ float g_y3[(size_t)MROWS * 64];
__device__ float g_xpf[(size_t)MROWS * 96];
__device__ float g_xpb[(size_t)MROWS * 96];
__device__ float g_gru[(size_t)MROWS * 64];
__device__ float g_pooled[BB * 64];
__device__ float g_sums1[512];   // [sum(256) | sumsq(256)]
__device__ float g_sums2[256];
__device__ float g_sums3[128];
__device__ float g_sc1[256], g_sh1[256];
__device__ float g_sc2[128], g_sh2[128];
__device__ float g_sc3[64],  g_sh3[64];

// ---------------- zero the stat accumulators -------------------------------
__global__ void zero_stats_kernel(float* s1, float* s2, float* s3) {
    int i = threadIdx.x;
    if (i < 512) s1[i] = 0.f;
    if (i < 256) s2[i] = 0.f;
    if (i < 128) s3[i] = 0.f;
}

// ---------------- generic GEMM: C[M,N] = f(A[M,K]) @ W[N,K]^T + bias -------
// f(a,k) = doTransform ? relu(a*scale[k]+shift[k]) : a
// BM=128, BN=64, BK=16, 256 threads, each thread 8x4 outputs.
#define GBM 128
#define GBN 64
#define GBK 16

__global__ __launch_bounds__(256) void gemm_kernel(
    const float* __restrict__ A, const float* __restrict__ W,
    const float* __restrict__ bias,
    const float* __restrict__ scale, const float* __restrict__ shift,
    float* __restrict__ C, int M, int N, int K, int doTransform)
{
    __shared__ float As[GBM][GBK + 1];
    __shared__ float Ws[GBN][GBK + 1];

    int tid = threadIdx.x;
    int ty = tid >> 4;          // 0..15
    int tx = tid & 15;          // 0..15
    int bm0 = blockIdx.x * GBM;
    int bn0 = blockIdx.y * GBN;

    float acc[8][4];
#pragma unroll
    for (int i = 0; i < 8; i++)
#pragma unroll
        for (int j = 0; j < 4; j++) acc[i][j] = 0.f;

    for (int k0 = 0; k0 < K; k0 += GBK) {
        // load A tile (128 x 16), 8 elems per thread, coalesced over k
#pragma unroll
        for (int i = 0; i < 8; i++) {
            int idx = tid + i * 256;
            int r = idx >> 4;
            int c = idx & 15;
            float v = A[(size_t)(bm0 + r) * K + (k0 + c)];
            if (doTransform) {
                v = v * scale[k0 + c] + shift[k0 + c];
                v = v > 0.f ? v : 0.f;
            }
            As[r][c] = v;
        }
        // load W tile (64 x 16), 4 elems per thread, guard N
#pragma unroll
        for (int i = 0; i < 4; i++) {
            int idx = tid + i * 256;
            int r = idx >> 4;
            int c = idx & 15;
            int n = bn0 + r;
            Ws[r][c] = (n < N) ? W[(size_t)n * K + (k0 + c)] : 0.f;
        }
        __syncthreads();

#pragma unroll
        for (int k = 0; k < GBK; k++) {
            float a[8], b[4];
#pragma unroll
            for (int i = 0; i < 8; i++) a[i] = As[ty + 16 * i][k];
#pragma unroll
            for (int j = 0; j < 4; j++) b[j] = Ws[tx + 16 * j][k];
#pragma unroll
            for (int i = 0; i < 8; i++)
#pragma unroll
                for (int j = 0; j < 4; j++) acc[i][j] += a[i] * b[j];
        }
        __syncthreads();
    }

#pragma unroll
    for (int j = 0; j < 4; j++) {
        int n = bn0 + tx + 16 * j;
        if (n >= N) continue;
        float bv = bias[n];
#pragma unroll
        for (int i = 0; i < 8; i++) {
            C[(size_t)(bm0 + ty + 16 * i) * N + n] = acc[i][j] + bv;
        }
    }
}

// ---------------- per-column sum / sumsq ------------------------------------
// N must divide 256. grid.x blocks each handle (M/grid.x) rows.
__global__ __launch_bounds__(256) void colstats_kernel(
    const float* __restrict__ Y, int M, int N, int rowsPerBlock,
    float* __restrict__ sums)
{
    int tid = threadIdx.x;
    int c = tid % N;
    int ro = tid / N;
    int rstride = 256 / N;
    int r0 = blockIdx.x * rowsPerBlock;
    float s = 0.f, sq = 0.f;
    for (int r = r0 + ro; r < r0 + rowsPerBlock; r += rstride) {
        float v = Y[(size_t)r * N + c];
        s += v;
        sq += v * v;
    }
    atomicAdd(&sums[c], s);
    atomicAdd(&sums[N + c], sq);
}

// ---------------- finalize BN affine ----------------------------------------
__global__ void finalize_bn_kernel(const float* __restrict__ sums,
                                   const float* __restrict__ gamma,
                                   const float* __restrict__ beta,
                                   float* __restrict__ scale,
                                   float* __restrict__ shift,
                                   int N, float invM)
{
    int c = blockIdx.x * blockDim.x + threadIdx.x;
    if (c < N) {
        float m = sums[c] * invM;
        float v = sums[N + c] * invM - m * m;
        float sc = gamma[c] * rsqrtf(v + EPSBN);
        scale[c] = sc;
        shift[c] = beta[c] - m * sc;
    }
}

// ---------------- GRU recurrence (one warp per (batch, direction)) ----------
__global__ __launch_bounds__(32) void gru_kernel(
    const float* __restrict__ xp_f, const float* __restrict__ xp_b,
    const float* __restrict__ Whh_f, const float* __restrict__ bhh_f,
    const float* __restrict__ Whh_b, const float* __restrict__ bhh_b,
    float* __restrict__ gru_out)
{
    int b = blockIdx.x;
    int dir = blockIdx.y;
    int j = threadIdx.x;   // 0..31

    const float* xp  = dir ? xp_b  : xp_f;
    const float* Whh = dir ? Whh_b : Whh_f;
    const float* bhh = dir ? bhh_b : bhh_f;

    float Wr[32], Wz[32], Wn[32];
#pragma unroll
    for (int k = 0; k < 32; k++) {
        Wr[k] = Whh[j * 32 + k];
        Wz[k] = Whh[(32 + j) * 32 + k];
        Wn[k] = Whh[(64 + j) * 32 + k];
    }
    float br = bhh[j], bz = bhh[32 + j], bnn = bhh[64 + j];

    float h = 0.f;
    size_t base = (size_t)b * TT * 96;
    int t = dir ? (TT - 1) : 0;
    int step = dir ? -1 : 1;

    // prefetch step 0
    float xr = xp[base + (size_t)t * 96 + j];
    float xz = xp[base + (size_t)t * 96 + 32 + j];
    float xn = xp[base + (size_t)t * 96 + 64 + j];

    for (int it = 0; it < TT; it++) {
        int tn = t + step;
        float nxr = 0.f, nxz = 0.f, nxn = 0.f;
        if (it + 1 < TT) {
            nxr = xp[base + (size_t)tn * 96 + j];
            nxz = xp[base + (size_t)tn * 96 + 32 + j];
            nxn = xp[base + (size_t)tn * 96 + 64 + j];
        }
        float accr = br, accz = bz, accn = bnn;
#pragma unroll
        for (int k = 0; k < 32; k++) {
            float hk = __shfl_sync(0xffffffffu, h, k);
            accr += Wr[k] * hk;
            accz += Wz[k] * hk;
            accn += Wn[k] * hk;
        }
        float r = 1.f / (1.f + __expf(-(xr + accr)));
        float z = 1.f / (1.f + __expf(-(xz + accz)));
        float n = tanhf(xn + r * accn);
        h = (1.f - z) * n + z * h;
        gru_out[((size_t)b * TT + t) * 64 + dir * 32 + j] = h;
        xr = nxr; xz = nxz; xn = nxn;
        t = tn;
    }
}

// ---------------- attention + softmax pooling (one block per batch) ---------
__global__ __launch_bounds__(256) void attn_kernel(
    const float* __restrict__ gru,
    const float* __restrict__ Wa1, const float* __restrict__ ba1,
    const float* __restrict__ Wa2, const float* __restrict__ ba2,
    float* __restrict__ pooled)
{
    __shared__ float s_scores[TT];
    __shared__ float s_Wa1[32 * 64];
    __shared__ float s_red[8];
    __shared__ float s_bcast[2];      // [0]=max, [1]=sumexp
    __shared__ float s_pool[4][64];

    int b = blockIdx.x;
    int tid = threadIdx.x;
    int lane = tid & 31;
    int w = tid >> 5;

    for (int i = tid; i < 32 * 64; i += 256) s_Wa1[i] = Wa1[i];
    __syncthreads();

    const float* gb = gru + (size_t)b * TT * 64;
    float wa2 = Wa2[lane];
    float ba2v = ba2[0];
    float ba1v = ba1[lane];

    for (int t = w; t < TT; t += 8) {
        const float* g = gb + (size_t)t * 64;
        float acc = ba1v;
#pragma unroll
        for (int k = 0; k < 64; k++) acc += s_Wa1[lane * 64 + k] * g[k];
        float v = tanhf(acc) * wa2;
#pragma unroll
        for (int o = 16; o; o >>= 1) v += __shfl_xor_sync(0xffffffffu, v, o);
        if (lane == 0) s_scores[t] = v + ba2v;
    }
    __syncthreads();

    // block max
    float m = -1e30f;
    for (int t = tid; t < TT; t += 256) m = fmaxf(m, s_scores[t]);
#pragma unroll
    for (int o = 16; o; o >>= 1) m = fmaxf(m, __shfl_xor_sync(0xffffffffu, m, o));
    if (lane == 0) s_red[w] = m;
    __syncthreads();
    if (tid == 0) {
        float mm = s_red[0];
#pragma unroll
        for (int i = 1; i < 8; i++) mm = fmaxf(mm, s_red[i]);
        s_bcast[0] = mm;
    }
    __syncthreads();
    m = s_bcast[0];

    // exp + sum
    float sum = 0.f;
    for (int t = tid; t < TT; t += 256) {
        float e = __expf(s_scores[t] - m);
        s_scores[t] = e;
        sum += e;
    }
#pragma unroll
    for (int o = 16; o; o >>= 1) sum += __shfl_xor_sync(0xffffffffu, sum, o);
    if (lane == 0) s_red[w] = sum;
    __syncthreads();
    if (tid == 0) {
        float ss = 0.f;
#pragma unroll
        for (int i = 0; i < 8; i++) ss += s_red[i];
        s_bcast[1] = ss;
    }
    __syncthreads();
    float sumexp = s_bcast[1];

    // weighted pool
    int c = tid & 63;
    int grp = tid >> 6;    // 0..3
    float acc = 0.f;
    for (int t = grp; t < TT; t += 4) acc += s_scores[t] * gb[(size_t)t * 64 + c];
    s_pool[grp][c] = acc;
    __syncthreads();
    if (tid < 64) {
        float tot = s_pool[0][tid] + s_pool[1][tid] + s_pool[2][tid] + s_pool[3][tid];
        pooled[b * 64 + tid] = tot / sumexp;
    }
}

// ---------------- classifier (single block, 128 threads = rows) -------------
__global__ __launch_bounds__(128) void cls_kernel(
    const float* __restrict__ pooled,
    const float* __restrict__ Wc1, const float* __restrict__ bc1,
    const float* __restrict__ gc, const float* __restrict__ bec,
    const float* __restrict__ Wc2, const float* __restrict__ bc2,
    float* __restrict__ out)
{
    __shared__ float s_sum[32], s_sq[32], s_scale[32], s_shift[32];
    int r = threadIdx.x;   // 0..127
    if (r < 32) { s_sum[r] = 0.f; s_sq[r] = 0.f; }
    __syncthreads();

    float x[64];
#pragma unroll
    for (int k = 0; k < 64; k++) x[k] = pooled[r * 64 + k];

    float q[32];
#pragma unroll
    for (int u = 0; u < 32; u++) {
        float a = bc1[u];
#pragma unroll
        for (int k = 0; k < 64; k++) a += Wc1[u * 64 + k] * x[k];
        q[u] = a;
        atomicAdd(&s_sum[u], a);
        atomicAdd(&s_sq[u], a * a);
    }
    __syncthreads();
    if (r < 32) {
        float m = s_sum[r] * (1.f / 128.f);
        float v = s_sq[r] * (1.f / 128.f) - m * m;
        float sc = gc[r] * rsqrtf(v + EPSBN);
        s_scale[r] = sc;
        s_shift[r] = bec[r] - m * sc;
    }
    __syncthreads();

    float qn[32];
#pragma unroll
    for (int u = 0; u < 32; u++) {
        float t = q[u] * s_scale[u] + s_shift[u];
        qn[u] = t > 0.f ? t : 0.f;
    }
#pragma unroll
    for (int c = 0; c < NCLS; c++) {
        float a = bc2[c];
#pragma unroll
        for (int k = 0; k < 32; k++) a += Wc2[c * 32 + k] * qn[k];
        out[r * NCLS + c] = a;
    }
}

// ---------------- launch ----------------------------------------------------
extern "C" void kernel_launch(void* const* d_in, const int* in_sizes, int n_in,
                              void* d_out, int out_size)
{
    (void)in_sizes; (void)n_in; (void)out_size;

    const float* x     = (const float*)d_in[0];
    const float* W1    = (const float*)d_in[1];
    const float* b1    = (const float*)d_in[2];
    const float* g1    = (const float*)d_in[3];
    const float* be1   = (const float*)d_in[4];
    const float* W2    = (const float*)d_in[5];
    const float* b2    = (const float*)d_in[6];
    const float* g2    = (const float*)d_in[7];
    const float* be2   = (const float*)d_in[8];
    const float* W3    = (const float*)d_in[9];
    const float* b3    = (const float*)d_in[10];
    const float* g3    = (const float*)d_in[11];
    const float* be3   = (const float*)d_in[12];
    const float* Wih_f = (const float*)d_in[13];
    const float* Whh_f = (const float*)d_in[14];
    const float* bih_f = (const float*)d_in[15];
    const float* bhh_f = (const float*)d_in[16];
    const float* Wih_b = (const float*)d_in[17];
    const float* Whh_b = (const float*)d_in[18];
    const float* bih_b = (const float*)d_in[19];
    const float* bhh_b = (const float*)d_in[20];
    const float* Wa1   = (const float*)d_in[21];
    const float* ba1   = (const float*)d_in[22];
    const float* Wa2   = (const float*)d_in[23];
    const float* ba2   = (const float*)d_in[24];
    const float* Wc1   = (const float*)d_in[25];
    const float* bc1   = (const float*)d_in[26];
    const float* gc    = (const float*)d_in[27];
    const float* bec   = (const float*)d_in[28];
    const float* Wc2   = (const float*)d_in[29];
    const float* bc2   = (const float*)d_in[30];
    float* out = (float*)d_out;

    // resolve scratch symbols (immediate API, capture-safe)
    float *y1, *y2, *y3, *xpf, *xpb, *gru, *pooled;
    float *sums1, *sums2, *sums3, *sc1, *sh1, *sc2, *sh2, *sc3, *sh3;
    cudaGetSymbolAddress((void**)&y1, g_y1);
    cudaGetSymbolAddress((void**)&y2, g_y2);
    cudaGetSymbolAddress((void**)&y3, g_y3);
    cudaGetSymbolAddress((void**)&xpf, g_xpf);
    cudaGetSymbolAddress((void**)&xpb, g_xpb);
    cudaGetSymbolAddress((void**)&gru, g_gru);
    cudaGetSymbolAddress((void**)&pooled, g_pooled);
    cudaGetSymbolAddress((void**)&sums1, g_sums1);
    cudaGetSymbolAddress((void**)&sums2, g_sums2);
    cudaGetSymbolAddress((void**)&sums3, g_sums3);
    cudaGetSymbolAddress((void**)&sc1, g_sc1);
    cudaGetSymbolAddress((void**)&sh1, g_sh1);
    cudaGetSymbolAddress((void**)&sc2, g_sc2);
    cudaGetSymbolAddress((void**)&sh2, g_sh2);
    cudaGetSymbolAddress((void**)&sc3, g_sc3);
    cudaGetSymbolAddress((void**)&sh3, g_sh3);

    const float invM = 1.f / (float)MROWS;

    zero_stats_kernel<<<1, 512>>>(sums1, sums2, sums3);

    // L1: y1 = x @ W1^T + b1     (M=262144, N=256, K=80)
    gemm_kernel<<<dim3(MROWS / GBM, 4), 256>>>(x, W1, b1, nullptr, nullptr,
                                               y1, MROWS, 256, FF, 0);
    colstats_kernel<<<1024, 256>>>(y1, MROWS, 256, MROWS / 1024, sums1);
    finalize_bn_kernel<<<1, 256>>>(sums1, g1, be1, sc1, sh1, 256, invM);

    // L2: y2 = relu(bn1(y1)) @ W2^T + b2   (N=128, K=256)
    gemm_kernel<<<dim3(MROWS / GBM, 2), 256>>>(y1, W2, b2, sc1, sh1,
                                               y2, MROWS, 128, 256, 1);
    colstats_kernel<<<1024, 256>>>(y2, MROWS, 128, MROWS / 1024, sums2);
    finalize_bn_kernel<<<1, 128>>>(sums2, g2, be2, sc2, sh2, 128, invM);

    // L3: y3 = relu(bn2(y2)) @ W3^T + b3   (N=64, K=128)
    gemm_kernel<<<dim3(MROWS / GBM, 1), 256>>>(y2, W3, b3, sc2, sh2,
                                               y3, MROWS, 64, 128, 1);
    colstats_kernel<<<1024, 256>>>(y3, MROWS, 64, MROWS / 1024, sums3);
    finalize_bn_kernel<<<1, 64>>>(sums3, g3, be3, sc3, sh3, 64, invM);

    // GRU input projections: xp = relu(bn3(y3)) @ Wih^T + bih   (N=96, K=64)
    gemm_kernel<<<dim3(MROWS / GBM, 2), 256>>>(y3, Wih_f, bih_f, sc3, sh3,
                                               xpf, MROWS, 96, 64, 1);
    gemm_kernel<<<dim3(MROWS / GBM, 2), 256>>>(y3, Wih_b, bih_b, sc3, sh3,
                                               xpb, MROWS, 96, 64, 1);

    // GRU recurrence (both directions)
    gru_kernel<<<dim3(BB, 2), 32>>>(xpf, xpb, Whh_f, bhh_f, Whh_b, bhh_b, gru);

    // attention pooling
    attn_kernel<<<BB, 256>>>(gru, Wa1, ba1, Wa2, ba2, pooled);

    // classifier
    cls_kernel<<<1, 128>>>(pooled, Wc1, bc1, gc, bec, Wc2, bc2, out);
}